// round 11
// baseline (speedup 1.0000x reference)
#include <cuda_runtime.h>
#include <math.h>

#define POOL 7
#define C 256

typedef unsigned long long u64;

__device__ __forceinline__ u64 f32x2_mul(u64 a, u64 b) {
    u64 d; asm("mul.rn.f32x2 %0, %1, %2;" : "=l"(d) : "l"(a), "l"(b)); return d;
}
__device__ __forceinline__ u64 f32x2_fma(u64 a, u64 b, u64 c) {
    u64 d; asm("fma.rn.f32x2 %0, %1, %2, %3;" : "=l"(d) : "l"(a), "l"(b), "l"(c)); return d;
}
__device__ __forceinline__ u64 f32x2_pack(float v) {
    u64 d; asm("mov.b64 %0, {%1, %1};" : "=l"(d) : "f"(v)); return d;
}
__device__ __forceinline__ u64 bilerp2(u64 v00, u64 v01, u64 v10, u64 v11,
                                       u64 wtx2, u64 tx2, u64 wty2, u64 ty2) {
    u64 top = f32x2_fma(v01, tx2, f32x2_mul(v00, wtx2));
    u64 bot = f32x2_fma(v11, tx2, f32x2_mul(v10, wtx2));
    return f32x2_fma(bot, ty2, f32x2_mul(top, wty2));
}

// One block per ROI (R6 structure — best known). Block (32,7): warp = pooled
// row, lane = channel quad (covers quads lane and lane+32). Column-carry walk
// over the 7 pooled columns (x0 non-decreasing, block-uniform).
// New in R11: a block barrier at the top of each px step time-aligns the
// warps' load bursts so duplicate lines (warp py's row1 == warp py+1's row0
// at the same block-uniform x column, when the ROI's y-step < 2) merge in
// MSHR / hit L1 instead of paying LTS bandwidth twice.
__global__ __launch_bounds__(224, 4)
void roi_align_kernel(const float* __restrict__ rois,
                      const int*   __restrict__ image_shape,
                      const float* __restrict__ p2,
                      const float* __restrict__ p3,
                      const float* __restrict__ p4,
                      const float* __restrict__ p5,
                      float* __restrict__ out,
                      int N)
{
    const int bn = blockIdx.x;
    const int b  = bn / N;

    const float4 r = reinterpret_cast<const float4*>(rois)[bn];
    const float y1 = r.x, x1 = r.y, y2 = r.z, x2 = r.w;
    const float h = y2 - y1;
    const float w = x2 - x1;

    const float img_area = (float)image_shape[0] * (float)image_shape[1];
    const float scale = sqrtf(fmaxf(h * w, 1e-12f)) * (sqrtf(img_area) / 224.0f);
    int lvl = 4 + (int)rintf(log2f(scale));   // round-half-even == jnp.round
    lvl = min(max(lvl, 2), 5);

    const float* feat;
    int H;
    switch (lvl) {
        case 2:  feat = p2; H = 256; break;
        case 3:  feat = p3; H = 128; break;
        case 4:  feat = p4; H = 64;  break;
        default: feat = p5; H = 32;  break;
    }
    const float Hm1 = (float)(H - 1);
    const float Hm2 = (float)(H - 2);
    feat += (size_t)b * (size_t)H * (size_t)H * C;

    const int lane = threadIdx.x;   // channel quad (and +32)
    const int py   = threadIdx.y;   // pooled row (warp-uniform)

    // ---- y coordinate (warp-uniform) ----
    const float gy  = (float)py * (1.0f / (POOL - 1));
    const float ysf = (y1 + gy * h) * Hm1;
    const float y0f = fminf(fmaxf(floorf(ysf), 0.0f), Hm2);
    const int   y0  = (int)y0f;
    const float ty  = fminf(fmaxf(ysf - y0f, 0.0f), 1.0f);
    const u64 wty2 = f32x2_pack(1.0f - ty);
    const u64 ty2  = f32x2_pack(ty);

    const ulonglong2* row0 = reinterpret_cast<const ulonglong2*>(feat) +
                             (size_t)y0 * H * 64 + lane;
    const ulonglong2* row1 = row0 + (size_t)H * 64;

    // ---- precompute 7 x offsets (quad units, non-decreasing) + fractions ----
    int   xo[POOL];
    float txa[POOL];
#pragma unroll
    for (int px = 0; px < POOL; ++px) {
        const float gx  = (float)px * (1.0f / (POOL - 1));
        const float xsf = (x1 + gx * w) * Hm1;
        const float x0f = fminf(fmaxf(floorf(xsf), 0.0f), Hm2);
        xo[px]  = (int)x0f * 64;
        txa[px] = fminf(fmaxf(xsf - x0f, 0.0f), 1.0f);
    }

    float4* out_base = reinterpret_cast<float4*>(out + (size_t)bn * (POOL * POOL * C))
                       + (size_t)py * POOL * 64 + lane;

    // Column-carry state: columns (cx, cx+1) for rows y0, y0+1; a = quad lane,
    // b = quad lane+32.
    ulonglong2 s00a, s00b, s01a, s01b, s10a, s10b, s11a, s11b;
    int cx = -128;   // sentinel: forces full load at px=0

#pragma unroll
    for (int px = 0; px < POOL; ++px) {
        // Align warps' load bursts for cross-warp line merging (row overlap).
        __syncthreads();

        const int x = xo[px];
        if (x == cx + 64) {
            // shift right column -> left, load one new column (4 LDG.128)
            s00a = s01a; s00b = s01b;
            s10a = s11a; s10b = s11b;
            const ulonglong2* q0 = row0 + (x + 64);
            const ulonglong2* q1 = row1 + (x + 64);
            s01a = q0[0]; s01b = q0[32];
            s11a = q1[0]; s11b = q1[32];
        } else if (x != cx) {
            // fresh pair of columns (8 LDG.128)
            const ulonglong2* q0 = row0 + x;
            const ulonglong2* q1 = row1 + x;
            s00a = q0[0];  s00b = q0[32];
            s01a = q0[64]; s01b = q0[96];
            s10a = q1[0];  s10b = q1[32];
            s11a = q1[64]; s11b = q1[96];
        }
        cx = x;

        const float tx = txa[px];
        const u64 wtx2 = f32x2_pack(1.0f - tx);
        const u64 tx2  = f32x2_pack(tx);

        ulonglong2 ra, rb;
        ra.x = bilerp2(s00a.x, s01a.x, s10a.x, s11a.x, wtx2, tx2, wty2, ty2);
        ra.y = bilerp2(s00a.y, s01a.y, s10a.y, s11a.y, wtx2, tx2, wty2, ty2);
        rb.x = bilerp2(s00b.x, s01b.x, s10b.x, s11b.x, wtx2, tx2, wty2, ty2);
        rb.y = bilerp2(s00b.y, s01b.y, s10b.y, s11b.y, wtx2, tx2, wty2, ty2);

        __stcs(out_base + px * 64,      *reinterpret_cast<float4*>(&ra));
        __stcs(out_base + px * 64 + 32, *reinterpret_cast<float4*>(&rb));
    }
}

extern "C" void kernel_launch(void* const* d_in, const int* in_sizes, int n_in,
                              void* d_out, int out_size)
{
    const float* rois        = (const float*)d_in[0];
    const int*   image_shape = (const int*)  d_in[1];
    const float* p2          = (const float*)d_in[2];
    const float* p3          = (const float*)d_in[3];
    const float* p4          = (const float*)d_in[4];
    const float* p5          = (const float*)d_in[5];
    float*       out         = (float*)d_out;

    const int B = in_sizes[2] / (256 * 256 * 256);
    const int N = in_sizes[0] / (4 * B);

    dim3 block(32, 7);
    dim3 grid(B * N);
    roi_align_kernel<<<grid, block>>>(rois, image_shape, p2, p3, p4, p5, out, N);
}

// round 12
// speedup vs baseline: 1.0294x; 1.0294x over previous
#include <cuda_runtime.h>
#include <math.h>

#define POOL 7
#define C 256

typedef unsigned long long u64;

__device__ __forceinline__ u64 f32x2_mul(u64 a, u64 b) {
    u64 d; asm("mul.rn.f32x2 %0, %1, %2;" : "=l"(d) : "l"(a), "l"(b)); return d;
}
__device__ __forceinline__ u64 f32x2_fma(u64 a, u64 b, u64 c) {
    u64 d; asm("fma.rn.f32x2 %0, %1, %2, %3;" : "=l"(d) : "l"(a), "l"(b), "l"(c)); return d;
}
__device__ __forceinline__ u64 f32x2_pack(float v) {
    u64 d; asm("mov.b64 %0, {%1, %1};" : "=l"(d) : "f"(v)); return d;
}
__device__ __forceinline__ u64 bilerp2(u64 v00, u64 v01, u64 v10, u64 v11,
                                       u64 wtx2, u64 tx2, u64 wty2, u64 ty2) {
    u64 top = f32x2_fma(v01, tx2, f32x2_mul(v00, wtx2));
    u64 bot = f32x2_fma(v11, tx2, f32x2_mul(v10, wtx2));
    return f32x2_fma(bot, ty2, f32x2_mul(top, wty2));
}

// Persistent grid-stride version of the best (R6) kernel: grid = min(592, BN)
// CTAs, each looping over ROIs with the identical R6 body. Removes wave
// quantization (2000 CTAs / 592 resident = 3.38 waves, 38%-full tail).
// Block (32,7): warp = pooled row, lane = channel quad (covers lane, lane+32).
// Column-carry walk over the 7 pooled columns (x0 non-decreasing, block-uniform).
__global__ __launch_bounds__(224, 4)
void roi_align_kernel(const float* __restrict__ rois,
                      const int*   __restrict__ image_shape,
                      const float* __restrict__ p2,
                      const float* __restrict__ p3,
                      const float* __restrict__ p4,
                      const float* __restrict__ p5,
                      float* __restrict__ out,
                      int N, int BN)
{
    const int lane = threadIdx.x;   // channel quad (and +32)
    const int py   = threadIdx.y;   // pooled row (warp-uniform)
    const float gy = (float)py * (1.0f / (POOL - 1));
    const float img_area = (float)image_shape[0] * (float)image_shape[1];
    const float lvl_bias = sqrtf(img_area) / 224.0f;

    for (int bn = blockIdx.x; bn < BN; bn += gridDim.x) {
        const int b = bn / N;

        const float4 r = reinterpret_cast<const float4*>(rois)[bn];
        const float y1 = r.x, x1 = r.y, y2 = r.z, x2 = r.w;
        const float h = y2 - y1;
        const float w = x2 - x1;

        const float scale = sqrtf(fmaxf(h * w, 1e-12f)) * lvl_bias;
        int lvl = 4 + (int)rintf(log2f(scale));   // round-half-even == jnp.round
        lvl = min(max(lvl, 2), 5);

        const float* feat;
        int H;
        switch (lvl) {
            case 2:  feat = p2; H = 256; break;
            case 3:  feat = p3; H = 128; break;
            case 4:  feat = p4; H = 64;  break;
            default: feat = p5; H = 32;  break;
        }
        const float Hm1 = (float)(H - 1);
        const float Hm2 = (float)(H - 2);
        const float* featb = feat + (size_t)b * (size_t)H * (size_t)H * C;

        // ---- y coordinate (warp-uniform) ----
        const float ysf = (y1 + gy * h) * Hm1;
        const float y0f = fminf(fmaxf(floorf(ysf), 0.0f), Hm2);
        const int   y0  = (int)y0f;
        const float ty  = fminf(fmaxf(ysf - y0f, 0.0f), 1.0f);
        const u64 wty2 = f32x2_pack(1.0f - ty);
        const u64 ty2  = f32x2_pack(ty);

        const ulonglong2* row0 = reinterpret_cast<const ulonglong2*>(featb) +
                                 (size_t)y0 * H * 64 + lane;
        const ulonglong2* row1 = row0 + (size_t)H * 64;

        // ---- precompute 7 x offsets (quad units, non-decreasing) + fractions ----
        int   xo[POOL];
        float txa[POOL];
#pragma unroll
        for (int px = 0; px < POOL; ++px) {
            const float gx  = (float)px * (1.0f / (POOL - 1));
            const float xsf = (x1 + gx * w) * Hm1;
            const float x0f = fminf(fmaxf(floorf(xsf), 0.0f), Hm2);
            xo[px]  = (int)x0f * 64;
            txa[px] = fminf(fmaxf(xsf - x0f, 0.0f), 1.0f);
        }

        float4* out_base = reinterpret_cast<float4*>(out + (size_t)bn * (POOL * POOL * C))
                           + (size_t)py * POOL * 64 + lane;

        // Column-carry state: columns (cx, cx+1) for rows y0, y0+1;
        // a = quad lane, b = quad lane+32.
        ulonglong2 s00a, s00b, s01a, s01b, s10a, s10b, s11a, s11b;
        int cx = -128;   // sentinel: forces full load at px=0

#pragma unroll
        for (int px = 0; px < POOL; ++px) {
            const int x = xo[px];
            if (x == cx + 64) {
                // shift right column -> left, load one new column (4 LDG.128)
                s00a = s01a; s00b = s01b;
                s10a = s11a; s10b = s11b;
                const ulonglong2* q0 = row0 + (x + 64);
                const ulonglong2* q1 = row1 + (x + 64);
                s01a = q0[0]; s01b = q0[32];
                s11a = q1[0]; s11b = q1[32];
            } else if (x != cx) {
                // fresh pair of columns (8 LDG.128)
                const ulonglong2* q0 = row0 + x;
                const ulonglong2* q1 = row1 + x;
                s00a = q0[0];  s00b = q0[32];
                s01a = q0[64]; s01b = q0[96];
                s10a = q1[0];  s10b = q1[32];
                s11a = q1[64]; s11b = q1[96];
            }
            cx = x;

            const float tx = txa[px];
            const u64 wtx2 = f32x2_pack(1.0f - tx);
            const u64 tx2  = f32x2_pack(tx);

            ulonglong2 ra, rb;
            ra.x = bilerp2(s00a.x, s01a.x, s10a.x, s11a.x, wtx2, tx2, wty2, ty2);
            ra.y = bilerp2(s00a.y, s01a.y, s10a.y, s11a.y, wtx2, tx2, wty2, ty2);
            rb.x = bilerp2(s00b.x, s01b.x, s10b.x, s11b.x, wtx2, tx2, wty2, ty2);
            rb.y = bilerp2(s00b.y, s01b.y, s10b.y, s11b.y, wtx2, tx2, wty2, ty2);

            __stcs(out_base + px * 64,      *reinterpret_cast<float4*>(&ra));
            __stcs(out_base + px * 64 + 32, *reinterpret_cast<float4*>(&rb));
        }
    }
}

extern "C" void kernel_launch(void* const* d_in, const int* in_sizes, int n_in,
                              void* d_out, int out_size)
{
    const float* rois        = (const float*)d_in[0];
    const int*   image_shape = (const int*)  d_in[1];
    const float* p2          = (const float*)d_in[2];
    const float* p3          = (const float*)d_in[3];
    const float* p4          = (const float*)d_in[4];
    const float* p5          = (const float*)d_in[5];
    float*       out         = (float*)d_out;

    const int B  = in_sizes[2] / (256 * 256 * 256);
    const int N  = in_sizes[0] / (4 * B);
    const int BN = B * N;

    // Persistent: one wave of CTAs (148 SMs x 4 resident), grid-stride over ROIs.
    int grid = 148 * 4;
    if (grid > BN) grid = BN;

    dim3 block(32, 7);
    roi_align_kernel<<<grid, block>>>(rois, image_shape, p2, p3, p4, p5, out, N, BN);
}

// round 13
// speedup vs baseline: 1.1125x; 1.0808x over previous
#include <cuda_runtime.h>
#include <math.h>

#define POOL 7
#define C 256

typedef unsigned long long u64;

__device__ __forceinline__ u64 f32x2_mul(u64 a, u64 b) {
    u64 d; asm("mul.rn.f32x2 %0, %1, %2;" : "=l"(d) : "l"(a), "l"(b)); return d;
}
__device__ __forceinline__ u64 f32x2_fma(u64 a, u64 b, u64 c) {
    u64 d; asm("fma.rn.f32x2 %0, %1, %2, %3;" : "=l"(d) : "l"(a), "l"(b), "l"(c)); return d;
}
__device__ __forceinline__ u64 f32x2_pack(float v) {
    u64 d; asm("mov.b64 %0, {%1, %1};" : "=l"(d) : "f"(v)); return d;
}
__device__ __forceinline__ u64 bilerp2(u64 v00, u64 v01, u64 v10, u64 v11,
                                       u64 wtx2, u64 tx2, u64 wty2, u64 ty2) {
    u64 top = f32x2_fma(v01, tx2, f32x2_mul(v00, wtx2));
    u64 bot = f32x2_fma(v11, tx2, f32x2_mul(v10, wtx2));
    return f32x2_fma(bot, ty2, f32x2_mul(top, wty2));
}

// One block per ROI. Block (32,7): warp = pooled row, lane = channel quad
// (covers quads lane and lane+32). Column-carry: since x0[] is non-decreasing
// and block-uniform, walking px left->right lets each cell reuse the previous
// cell's right column as its left column (register shift), cutting requested
// read bytes ~40-45%. All carry branches are warp-uniform (no divergence).
// Empirically the LTS-byte-floor optimum for this problem (see R6-R12 audit).
__global__ __launch_bounds__(224, 4)
void roi_align_kernel(const float* __restrict__ rois,
                      const int*   __restrict__ image_shape,
                      const float* __restrict__ p2,
                      const float* __restrict__ p3,
                      const float* __restrict__ p4,
                      const float* __restrict__ p5,
                      float* __restrict__ out,
                      int N)
{
    const int bn = blockIdx.x;
    const int b  = bn / N;

    const float4 r = reinterpret_cast<const float4*>(rois)[bn];
    const float y1 = r.x, x1 = r.y, y2 = r.z, x2 = r.w;
    const float h = y2 - y1;
    const float w = x2 - x1;

    const float img_area = (float)image_shape[0] * (float)image_shape[1];
    const float scale = sqrtf(fmaxf(h * w, 1e-12f)) * (sqrtf(img_area) / 224.0f);
    int lvl = 4 + (int)rintf(log2f(scale));   // round-half-even == jnp.round
    lvl = min(max(lvl, 2), 5);

    const float* feat;
    int H;
    switch (lvl) {
        case 2:  feat = p2; H = 256; break;
        case 3:  feat = p3; H = 128; break;
        case 4:  feat = p4; H = 64;  break;
        default: feat = p5; H = 32;  break;
    }
    const float Hm1 = (float)(H - 1);
    const float Hm2 = (float)(H - 2);
    feat += (size_t)b * (size_t)H * (size_t)H * C;

    const int lane = threadIdx.x;   // channel quad (and +32)
    const int py   = threadIdx.y;   // pooled row (warp-uniform)

    // ---- y coordinate (warp-uniform) ----
    const float gy  = (float)py * (1.0f / (POOL - 1));
    const float ysf = (y1 + gy * h) * Hm1;
    const float y0f = fminf(fmaxf(floorf(ysf), 0.0f), Hm2);
    const int   y0  = (int)y0f;
    const float ty  = fminf(fmaxf(ysf - y0f, 0.0f), 1.0f);
    const u64 wty2 = f32x2_pack(1.0f - ty);
    const u64 ty2  = f32x2_pack(ty);

    const ulonglong2* row0 = reinterpret_cast<const ulonglong2*>(feat) +
                             (size_t)y0 * H * 64 + lane;
    const ulonglong2* row1 = row0 + (size_t)H * 64;

    // ---- precompute 7 x offsets (quad units, non-decreasing) + fractions ----
    int   xo[POOL];
    float txa[POOL];
#pragma unroll
    for (int px = 0; px < POOL; ++px) {
        const float gx  = (float)px * (1.0f / (POOL - 1));
        const float xsf = (x1 + gx * w) * Hm1;
        const float x0f = fminf(fmaxf(floorf(xsf), 0.0f), Hm2);
        xo[px]  = (int)x0f * 64;
        txa[px] = fminf(fmaxf(xsf - x0f, 0.0f), 1.0f);
    }

    float4* out_base = reinterpret_cast<float4*>(out + (size_t)bn * (POOL * POOL * C))
                       + (size_t)py * POOL * 64 + lane;

    // Column-carry state: columns (cx, cx+1) for rows y0, y0+1; a = quad lane,
    // b = quad lane+32.
    ulonglong2 s00a, s00b, s01a, s01b, s10a, s10b, s11a, s11b;
    int cx = -128;   // sentinel: forces full load at px=0

#pragma unroll
    for (int px = 0; px < POOL; ++px) {
        const int x = xo[px];
        if (x == cx + 64) {
            // shift right column -> left, load one new column (4 LDG.128)
            s00a = s01a; s00b = s01b;
            s10a = s11a; s10b = s11b;
            const ulonglong2* q0 = row0 + (x + 64);
            const ulonglong2* q1 = row1 + (x + 64);
            s01a = q0[0]; s01b = q0[32];
            s11a = q1[0]; s11b = q1[32];
        } else if (x != cx) {
            // fresh pair of columns (8 LDG.128)
            const ulonglong2* q0 = row0 + x;
            const ulonglong2* q1 = row1 + x;
            s00a = q0[0];  s00b = q0[32];
            s01a = q0[64]; s01b = q0[96];
            s10a = q1[0];  s10b = q1[32];
            s11a = q1[64]; s11b = q1[96];
        }
        cx = x;

        const float tx = txa[px];
        const u64 wtx2 = f32x2_pack(1.0f - tx);
        const u64 tx2  = f32x2_pack(tx);

        ulonglong2 ra, rb;
        ra.x = bilerp2(s00a.x, s01a.x, s10a.x, s11a.x, wtx2, tx2, wty2, ty2);
        ra.y = bilerp2(s00a.y, s01a.y, s10a.y, s11a.y, wtx2, tx2, wty2, ty2);
        rb.x = bilerp2(s00b.x, s01b.x, s10b.x, s11b.x, wtx2, tx2, wty2, ty2);
        rb.y = bilerp2(s00b.y, s01b.y, s10b.y, s11b.y, wtx2, tx2, wty2, ty2);

        __stcs(out_base + px * 64,      *reinterpret_cast<float4*>(&ra));
        __stcs(out_base + px * 64 + 32, *reinterpret_cast<float4*>(&rb));
    }
}

extern "C" void kernel_launch(void* const* d_in, const int* in_sizes, int n_in,
                              void* d_out, int out_size)
{
    const float* rois        = (const float*)d_in[0];
    const int*   image_shape = (const int*)  d_in[1];
    const float* p2          = (const float*)d_in[2];
    const float* p3          = (const float*)d_in[3];
    const float* p4          = (const float*)d_in[4];
    const float* p5          = (const float*)d_in[5];
    float*       out         = (float*)d_out;

    const int B = in_sizes[2] / (256 * 256 * 256);
    const int N = in_sizes[0] / (4 * B);

    dim3 block(32, 7);
    dim3 grid(B * N);
    roi_align_kernel<<<grid, block>>>(rois, image_shape, p2, p3, p4, p5, out, N);
}